// round 3
// baseline (speedup 1.0000x reference)
#include <cuda_runtime.h>
#include <cuda_bf16.h>
#include <math.h>

// Problem constants
#define BSZ   2
#define SEQ   2048
#define NH    16
#define HD    128
#define HID   2048
#define MROWS (BSZ*SEQ)           // 4096
#define MN    ((size_t)MROWS*HID) // 8388608
#define NZ    (BSZ*NH)            // 32 (b,h) pairs

// ---------------- scratch (device globals; no allocation allowed) -------------
__device__ float g_qkv[3*MROWS*HID];            // raw Q,K,V projections [3][B*S, H*D]
__device__ float g_q[MROWS*HID];                // [B,H,S,D] after RoPE
__device__ float g_k[MROWS*HID];
__device__ float g_v[MROWS*HID];
__device__ float g_attn_t[MROWS*HID];           // attention out in [B*S, H*D]
__device__ float g_scores[(size_t)NZ*SEQ*SEQ];  // [B*H, S, S] scores/probs

// =====================================================================
// GEMM NT: C[M,N] = A[M,K] * B[N,K]^T   (A, B row-major)
// 64x64 tile, BK=16, 256 threads, 4x4 per thread. Fresh derivation.
// =====================================================================
__device__ __forceinline__ void gemm64_nt(
    const float* __restrict__ A, const float* __restrict__ B, float* __restrict__ C,
    int K, int ldc)
{
    __shared__ float As[64][17];   // [row][k]
    __shared__ float Bs[64][17];   // [row(N)][k]

    const int tid  = threadIdx.x;
    const int arow = tid >> 2;          // 0..63
    const int acol = (tid & 3) << 2;    // 0,4,8,12
    const int ty   = tid >> 4;          // 0..15 -> C rows ty*4..ty*4+3
    const int tx   = tid & 15;          // 0..15 -> C cols tx*4..tx*4+3

    const float* Ag = A + ((size_t)blockIdx.y * 64 + arow) * K + acol;
    const float* Bg = B + ((size_t)blockIdx.x * 64 + arow) * K + acol;

    float acc[4][4];
    #pragma unroll
    for (int i = 0; i < 4; i++)
        #pragma unroll
        for (int j = 0; j < 4; j++) acc[i][j] = 0.0f;

    for (int k0 = 0; k0 < K; k0 += 16) {
        float4 a4 = *(const float4*)(Ag + k0);
        float4 b4 = *(const float4*)(Bg + k0);
        __syncthreads();
        As[arow][acol+0] = a4.x; As[arow][acol+1] = a4.y;
        As[arow][acol+2] = a4.z; As[arow][acol+3] = a4.w;
        Bs[arow][acol+0] = b4.x; Bs[arow][acol+1] = b4.y;
        Bs[arow][acol+2] = b4.z; Bs[arow][acol+3] = b4.w;
        __syncthreads();
        #pragma unroll
        for (int kk = 0; kk < 16; kk++) {
            float ar[4], br[4];
            #pragma unroll
            for (int i = 0; i < 4; i++) ar[i] = As[ty*4 + i][kk];
            #pragma unroll
            for (int j = 0; j < 4; j++) br[j] = Bs[tx*4 + j][kk];
            #pragma unroll
            for (int i = 0; i < 4; i++)
                #pragma unroll
                for (int j = 0; j < 4; j++)
                    acc[i][j] = fmaf(ar[i], br[j], acc[i][j]);
        }
    }

    #pragma unroll
    for (int i = 0; i < 4; i++) {
        size_t row = (size_t)blockIdx.y * 64 + ty*4 + i;
        float* Cr = C + row * (size_t)ldc + (size_t)blockIdx.x * 64 + tx*4;
        #pragma unroll
        for (int j = 0; j < 4; j++) Cr[j] = acc[i][j];
    }
}

// =====================================================================
// GEMM NN: C[M,N] = A[M,K] * B[K,N]   (A, B row-major)
// Same tiling; B tile is [16 x 64].
// =====================================================================
__device__ __forceinline__ void gemm64_nn(
    const float* __restrict__ A, const float* __restrict__ B, float* __restrict__ C,
    int N, int K, int ldc)
{
    __shared__ float As[64][17];   // [row][k]
    __shared__ float Bs[16][68];   // [k][col]

    const int tid   = threadIdx.x;
    const int arow  = tid >> 2;         // 0..63
    const int acol  = (tid & 3) << 2;   // 0,4,8,12
    const int bkrow = tid >> 4;         // 0..15
    const int bcol  = (tid & 15) << 2;  // 0..60
    const int ty    = tid >> 4;
    const int tx    = tid & 15;

    const float* Ag = A + ((size_t)blockIdx.y * 64 + arow) * K + acol;
    const float* Bg = B + (size_t)blockIdx.x * 64 + bcol;

    float acc[4][4];
    #pragma unroll
    for (int i = 0; i < 4; i++)
        #pragma unroll
        for (int j = 0; j < 4; j++) acc[i][j] = 0.0f;

    for (int k0 = 0; k0 < K; k0 += 16) {
        float4 a4 = *(const float4*)(Ag + k0);
        float4 b4 = *(const float4*)(Bg + (size_t)(k0 + bkrow) * N);
        __syncthreads();
        As[arow][acol+0] = a4.x; As[arow][acol+1] = a4.y;
        As[arow][acol+2] = a4.z; As[arow][acol+3] = a4.w;
        Bs[bkrow][bcol+0] = b4.x; Bs[bkrow][bcol+1] = b4.y;
        Bs[bkrow][bcol+2] = b4.z; Bs[bkrow][bcol+3] = b4.w;
        __syncthreads();
        #pragma unroll
        for (int kk = 0; kk < 16; kk++) {
            float ar[4], br[4];
            #pragma unroll
            for (int i = 0; i < 4; i++) ar[i] = As[ty*4 + i][kk];
            #pragma unroll
            for (int j = 0; j < 4; j++) br[j] = Bs[kk][tx*4 + j];
            #pragma unroll
            for (int i = 0; i < 4; i++)
                #pragma unroll
                for (int j = 0; j < 4; j++)
                    acc[i][j] = fmaf(ar[i], br[j], acc[i][j]);
        }
    }

    #pragma unroll
    for (int i = 0; i < 4; i++) {
        size_t row = (size_t)blockIdx.y * 64 + ty*4 + i;
        float* Cr = C + row * (size_t)ldc + (size_t)blockIdx.x * 64 + tx*4;
        #pragma unroll
        for (int j = 0; j < 4; j++) Cr[j] = acc[i][j];
    }
}

// ---------------- kernels ------------------------------------------------------
__global__ __launch_bounds__(256) void qkv_gemm_kernel(
    const float* __restrict__ X,
    const float* __restrict__ Wq,
    const float* __restrict__ Wk,
    const float* __restrict__ Wv)
{
    const float* W = (blockIdx.z == 0) ? Wq : (blockIdx.z == 1) ? Wk : Wv;
    float* C = g_qkv + (size_t)blockIdx.z * MN;
    gemm64_nt(X, W, C, HID, HID);
}

__global__ __launch_bounds__(256) void out_gemm_kernel(
    const float* __restrict__ Wo, float* __restrict__ out)
{
    gemm64_nt(g_attn_t, Wo, out, HID, HID);
}

// RoPE + transpose to [B,H,S,D]; one thread per (b,h,s,d<64). fp64 angles.
__global__ __launch_bounds__(256) void rope_transpose_kernel()
{
    long long idx = (long long)blockIdx.x * blockDim.x + threadIdx.x;
    const long long total = (long long)BSZ * NH * SEQ * 64;
    if (idx >= total) return;

    int d = (int)(idx % 64);  long long r = idx / 64;
    int s = (int)(r % SEQ);   r /= SEQ;
    int h = (int)(r % NH);
    int b = (int)(r / NH);

    // inv_freq = 10000^(-2d/128); angle = s * inv_freq   (double precision)
    double inv_freq = exp(-((double)(2 * d) / (double)HD) * log(10000.0));
    double ang = (double)s * inv_freq;
    double cd, sd;
    sincos(ang, &sd, &cd);
    float c  = (float)cd;
    float sn = (float)sd;

    size_t src = ((size_t)b * SEQ + s) * HID + (size_t)h * HD + d;   // [B*S, H*D]
    size_t dst = (((size_t)b * NH + h) * SEQ + s) * HD + d;          // [B,H,S,D]

    const float* Q0 = g_qkv;
    const float* K0 = g_qkv + MN;
    const float* V0 = g_qkv + 2 * MN;

    float q0 = Q0[src], q1 = Q0[src + 64];
    g_q[dst]      = q0 * c - q1 * sn;
    g_q[dst + 64] = q1 * c + q0 * sn;

    float k0 = K0[src], k1 = K0[src + 64];
    g_k[dst]      = k0 * c - k1 * sn;
    g_k[dst + 64] = k1 * c + k0 * sn;

    g_v[dst]      = V0[src];
    g_v[dst + 64] = V0[src + 64];
}

// scores[z,q,k] = Q[z,q,:] . K[z,k,:]   (raw, unscaled)
__global__ __launch_bounds__(256) void score_gemm_kernel()
{
    int z = blockIdx.z;
    const float* A = g_q + (size_t)z * SEQ * HD;
    const float* B = g_k + (size_t)z * SEQ * HD;
    float* C = g_scores + (size_t)z * SEQ * SEQ;
    gemm64_nt(A, B, C, HD, SEQ);
}

// warp-per-row softmax with scale + causal mask; normalized probs in place
__global__ __launch_bounds__(256) void softmax_kernel()
{
    const int warp = threadIdx.x >> 5;
    const int lane = threadIdx.x & 31;
    size_t row = (size_t)blockIdx.x * 8 + warp;            // 0 .. NZ*SEQ-1
    int q = (int)(row % SEQ);
    float* p = g_scores + row * (size_t)SEQ;
    const float scale = 0.08838834764831845f;              // 1/sqrt(128)

    float m = -INFINITY;
    for (int k = lane; k <= q; k += 32) m = fmaxf(m, p[k] * scale);
    #pragma unroll
    for (int o = 16; o; o >>= 1) m = fmaxf(m, __shfl_xor_sync(0xffffffffu, m, o));

    float ssum = 0.0f;
    for (int k = lane; k <= q; k += 32) ssum += expf(p[k] * scale - m);
    #pragma unroll
    for (int o = 16; o; o >>= 1) ssum += __shfl_xor_sync(0xffffffffu, ssum, o);

    float inv = 1.0f / ssum;
    for (int k = lane; k < SEQ; k += 32)
        p[k] = (k <= q) ? expf(p[k] * scale - m) * inv : 0.0f;
}

// O[z] = P[z] @ V[z], written directly into [B*S, H*D] layout
__global__ __launch_bounds__(256) void pv_gemm_kernel()
{
    int z = blockIdx.z;
    int b = z / NH, h = z % NH;
    const float* A = g_scores + (size_t)z * SEQ * SEQ;  // [S, S] probs
    const float* B = g_v + (size_t)z * SEQ * HD;        // [S, HD]
    float* C = g_attn_t + (size_t)b * SEQ * HID + (size_t)h * HD;
    gemm64_nn(A, B, C, HD, SEQ, HID);
}

// ---------------- launch -------------------------------------------------------
extern "C" void kernel_launch(void* const* d_in, const int* in_sizes, int n_in,
                              void* d_out, int out_size)
{
    // metadata order: hidden_states, Wq, Wk, Wv, Wo, attention_mask
    const float* X  = (const float*)d_in[0];
    const float* Wq = (const float*)d_in[1];
    const float* Wk = (const float*)d_in[2];
    const float* Wv = (const float*)d_in[3];
    const float* Wo = (const float*)d_in[4];
    float* out = (float*)d_out;

    // 1. QKV projections:  g_qkv[z] = X @ W^T
    {
        dim3 grid(HID / 64, MROWS / 64, 3);
        qkv_gemm_kernel<<<grid, 256>>>(X, Wq, Wk, Wv);
    }
    // 2. RoPE + transpose to [B,H,S,D]
    {
        long long total = (long long)BSZ * NH * SEQ * 64;  // 4,194,304
        rope_transpose_kernel<<<(unsigned)((total + 255) / 256), 256>>>();
    }
    // 3. Scores = Q K^T  (per b,h)
    {
        dim3 grid(SEQ / 64, SEQ / 64, NZ);
        score_gemm_kernel<<<grid, 256>>>();
    }
    // 4. Softmax (scale + causal mask), in place
    {
        unsigned rows = NZ * SEQ;                 // 65536
        softmax_kernel<<<rows / 8, 256>>>();
    }
    // 5. O = P V  -> directly [B*S, H*D]
    {
        dim3 grid(HD / 64, SEQ / 64, NZ);
        pv_gemm_kernel<<<grid, 256>>>();
    }
    // 6. Output projection: out = attn_t @ Wo^T
    {
        dim3 grid(HID / 64, MROWS / 64);
        out_gemm_kernel<<<grid, 256>>>(Wo, out);
    }
}

// round 7
// speedup vs baseline: 1.9449x; 1.9449x over previous
#include <cuda_runtime.h>
#include <cuda_bf16.h>
#include <math.h>
#include <stdint.h>
#include <mma.h>

using namespace nvcuda;

// Problem constants
#define BSZ   2
#define SEQ   2048
#define NH    16
#define HD    128
#define HID   2048
#define MROWS (BSZ*SEQ)           // 4096
#define MN    ((size_t)MROWS*HID) // 8388608
#define NZ    (BSZ*NH)            // 32 (b,h) pairs

#define BK    32
#define LDSA  40                  // smem leading dim for [row][k] tiles
#define LDSB  136                 // smem leading dim for [k][n] tiles (NN)

// ---------------- scratch (device globals; no allocation allowed) -------------
__device__ float g_qkv[3*MROWS*HID];            // raw Q,K,V projections [3][B*S, H*D]
__device__ float g_q[MROWS*HID];                // [B,H,S,D] after RoPE
__device__ float g_k[MROWS*HID];
__device__ float g_v[MROWS*HID];
__device__ float g_attn_t[MROWS*HID];           // attention out in [B*S, H*D]
__device__ float g_scores[(size_t)NZ*SEQ*SEQ];  // [B*H, S, S] scores/probs

// =====================================================================
// WMMA tf32 GEMM body. Block tile 128x128, BK=32, 256 threads (8 warps,
// 2x4), warp tile 64x32 (4x2 wmma m16n16k8 tiles).
//  - TRANSB=true : B is [N,K] row-major (C = A * B^T); matrix_b col_major
//  - TRANSB=false: B is [K,N] row-major (C = A * B);  matrix_b row_major
// kTiles = number of BK-wide K tiles (K = kTiles*BK).
// =====================================================================
template <bool TRANSB>
__device__ __forceinline__ void wmma_gemm_body(
    const float* __restrict__ A, const float* __restrict__ B, float* __restrict__ C,
    int lda, int ldb, int ldc, int m0, int n0, int kTiles,
    float* smA, float* smB)
{
    const int tid = threadIdx.x;
    const int wid = tid >> 5;
    const int warp_m = (wid >> 2) * 64;   // 0 or 64
    const int warp_n = (wid & 3) * 32;    // 0,32,64,96

    wmma::fragment<wmma::accumulator, 16, 16, 8, float> acc[4][2];
    #pragma unroll
    for (int mi = 0; mi < 4; mi++)
        #pragma unroll
        for (int ni = 0; ni < 2; ni++)
            wmma::fill_fragment(acc[mi][ni], 0.0f);

    for (int kt = 0; kt < kTiles; kt++) {
        const int k0 = kt * BK;

        // ---- stage A tile: 128 rows x 32 cols (tf32-rounded) ----
        #pragma unroll
        for (int r = 0; r < 4; r++) {
            int idx = tid + r * 256;       // 0..1023 float4s
            int row = idx >> 3;            // 0..127
            int c4  = (idx & 7) << 2;      // 0..28
            float4 v = *(const float4*)(A + (size_t)(m0 + row) * lda + k0 + c4);
            float* d = smA + row * LDSA + c4;
            d[0] = wmma::__float_to_tf32(v.x);
            d[1] = wmma::__float_to_tf32(v.y);
            d[2] = wmma::__float_to_tf32(v.z);
            d[3] = wmma::__float_to_tf32(v.w);
        }
        // ---- stage B tile ----
        if (TRANSB) {
            // B[N,K] row-major -> smB[n][k] (same pattern as A)
            #pragma unroll
            for (int r = 0; r < 4; r++) {
                int idx = tid + r * 256;
                int row = idx >> 3;        // n 0..127
                int c4  = (idx & 7) << 2;  // k 0..28
                float4 v = *(const float4*)(B + (size_t)(n0 + row) * ldb + k0 + c4);
                float* d = smB + row * LDSA + c4;
                d[0] = wmma::__float_to_tf32(v.x);
                d[1] = wmma::__float_to_tf32(v.y);
                d[2] = wmma::__float_to_tf32(v.z);
                d[3] = wmma::__float_to_tf32(v.w);
            }
        } else {
            // B[K,N] row-major -> smB[k][n], natural layout (no transpose)
            #pragma unroll
            for (int r = 0; r < 4; r++) {
                int idx = tid + r * 256;       // 0..1023 float4s
                int krow = idx >> 5;           // 0..31
                int c4   = (idx & 31) << 2;    // 0..124
                float4 v = *(const float4*)(B + (size_t)(k0 + krow) * ldb + n0 + c4);
                float* d = smB + krow * LDSB + c4;
                d[0] = wmma::__float_to_tf32(v.x);
                d[1] = wmma::__float_to_tf32(v.y);
                d[2] = wmma::__float_to_tf32(v.z);
                d[3] = wmma::__float_to_tf32(v.w);
            }
        }
        __syncthreads();

        // ---- compute: 4 k8 steps ----
        #pragma unroll
        for (int ks = 0; ks < BK; ks += 8) {
            wmma::fragment<wmma::matrix_a, 16, 16, 8, wmma::precision::tf32,
                           wmma::row_major> af[4];
            #pragma unroll
            for (int mi = 0; mi < 4; mi++)
                wmma::load_matrix_sync(af[mi], smA + (warp_m + mi * 16) * LDSA + ks, LDSA);

            if (TRANSB) {
                // B^T is [K,N] col-major over smB[n][k]: elem(k,n) at smB[n*LDSA + k]
                wmma::fragment<wmma::matrix_b, 16, 16, 8, wmma::precision::tf32,
                               wmma::col_major> bf[2];
                #pragma unroll
                for (int ni = 0; ni < 2; ni++)
                    wmma::load_matrix_sync(bf[ni], smB + (warp_n + ni * 16) * LDSA + ks, LDSA);
                #pragma unroll
                for (int mi = 0; mi < 4; mi++)
                    #pragma unroll
                    for (int ni = 0; ni < 2; ni++)
                        wmma::mma_sync(acc[mi][ni], af[mi], bf[ni], acc[mi][ni]);
            } else {
                wmma::fragment<wmma::matrix_b, 16, 16, 8, wmma::precision::tf32,
                               wmma::row_major> bf[2];
                #pragma unroll
                for (int ni = 0; ni < 2; ni++)
                    wmma::load_matrix_sync(bf[ni], smB + ks * LDSB + warp_n + ni * 16, LDSB);
                #pragma unroll
                for (int mi = 0; mi < 4; mi++)
                    #pragma unroll
                    for (int ni = 0; ni < 2; ni++)
                        wmma::mma_sync(acc[mi][ni], af[mi], bf[ni], acc[mi][ni]);
            }
        }
        __syncthreads();
    }

    // ---- store C ----
    #pragma unroll
    for (int mi = 0; mi < 4; mi++)
        #pragma unroll
        for (int ni = 0; ni < 2; ni++) {
            size_t row = (size_t)(m0 + warp_m + mi * 16);
            int col = n0 + warp_n + ni * 16;
            wmma::store_matrix_sync(C + row * ldc + col, acc[mi][ni], ldc,
                                    wmma::mem_row_major);
        }
}

// ---------------- GEMM kernels -------------------------------------------------
__global__ __launch_bounds__(256) void qkv_gemm_kernel(
    const float* __restrict__ X,
    const float* __restrict__ Wq,
    const float* __restrict__ Wk,
    const float* __restrict__ Wv)
{
    __shared__ float smA[128 * LDSA];
    __shared__ float smB[128 * LDSA];
    const float* W = (blockIdx.z == 0) ? Wq : (blockIdx.z == 1) ? Wk : Wv;
    float* C = g_qkv + (size_t)blockIdx.z * MN;
    wmma_gemm_body<true>(X, W, C, HID, HID, HID,
                         blockIdx.y * 128, blockIdx.x * 128, HID / BK, smA, smB);
}

__global__ __launch_bounds__(256) void out_gemm_kernel(
    const float* __restrict__ Wo, float* __restrict__ out)
{
    __shared__ float smA[128 * LDSA];
    __shared__ float smB[128 * LDSA];
    wmma_gemm_body<true>(g_attn_t, Wo, out, HID, HID, HID,
                         blockIdx.y * 128, blockIdx.x * 128, HID / BK, smA, smB);
}

// scores[z,q,k] = Q[z,q,:] . K[z,k,:] ; skip blocks fully above the diagonal
__global__ __launch_bounds__(256) void score_gemm_kernel()
{
    if (blockIdx.x > blockIdx.y) return;   // all k > all q in this block
    __shared__ float smA[128 * LDSA];
    __shared__ float smB[128 * LDSA];
    int z = blockIdx.z;
    const float* A = g_q + (size_t)z * SEQ * HD;
    const float* B = g_k + (size_t)z * SEQ * HD;
    float* C = g_scores + (size_t)z * SEQ * SEQ;
    wmma_gemm_body<true>(A, B, C, HD, HD, SEQ,
                         blockIdx.y * 128, blockIdx.x * 128, HD / BK, smA, smB);
}

// O[z] = P[z] @ V[z] -> [B*S, H*D]; K-loop truncated at the causal diagonal
__global__ __launch_bounds__(256) void pv_gemm_kernel()
{
    __shared__ float smA[128 * LDSA];
    __shared__ float smB[128 * LDSA];
    int z = blockIdx.z;
    int b = z / NH, h = z % NH;
    int m0 = blockIdx.y * 128;
    const float* A = g_scores + (size_t)z * SEQ * SEQ;   // [S,S] probs
    const float* B = g_v + (size_t)z * SEQ * HD;         // [S,HD]
    float* C = g_attn_t + (size_t)b * SEQ * HID + (size_t)h * HD;
    int kT = (m0 + 128) / BK;          // only k <= q contribute
    wmma_gemm_body<false>(A, B, C, SEQ, HD, HID, m0, 0, kT, smA, smB);
}

// ---------------- RoPE + transpose to [B,H,S,D] (Round-3 verified) -------------
__global__ __launch_bounds__(256) void rope_transpose_kernel()
{
    long long idx = (long long)blockIdx.x * blockDim.x + threadIdx.x;
    const long long total = (long long)BSZ * NH * SEQ * 64;
    if (idx >= total) return;

    int d = (int)(idx % 64);  long long r = idx / 64;
    int s = (int)(r % SEQ);   r /= SEQ;
    int h = (int)(r % NH);
    int b = (int)(r / NH);

    double inv_freq = exp(-((double)(2 * d) / (double)HD) * log(10000.0));
    double ang = (double)s * inv_freq;
    double cd, sd;
    sincos(ang, &sd, &cd);
    float c  = (float)cd;
    float sn = (float)sd;

    size_t src = ((size_t)b * SEQ + s) * HID + (size_t)h * HD + d;   // [B*S, H*D]
    size_t dst = (((size_t)b * NH + h) * SEQ + s) * HD + d;          // [B,H,S,D]

    const float* Q0 = g_qkv;
    const float* K0 = g_qkv + MN;
    const float* V0 = g_qkv + 2 * MN;

    float q0 = Q0[src], q1 = Q0[src + 64];
    g_q[dst]      = q0 * c - q1 * sn;
    g_q[dst + 64] = q1 * c + q0 * sn;

    float k0 = K0[src], k1 = K0[src + 64];
    g_k[dst]      = k0 * c - k1 * sn;
    g_k[dst + 64] = k1 * c + k0 * sn;

    g_v[dst]      = V0[src];
    g_v[dst + 64] = V0[src + 64];
}

// ---------------- softmax (Round-3 verified; only reads k <= q) ----------------
__global__ __launch_bounds__(256) void softmax_kernel()
{
    const int warp = threadIdx.x >> 5;
    const int lane = threadIdx.x & 31;
    size_t row = (size_t)blockIdx.x * 8 + warp;            // 0 .. NZ*SEQ-1
    int q = (int)(row % SEQ);
    float* p = g_scores + row * (size_t)SEQ;
    const float scale = 0.08838834764831845f;              // 1/sqrt(128)

    float m = -INFINITY;
    for (int k = lane; k <= q; k += 32) m = fmaxf(m, p[k] * scale);
    #pragma unroll
    for (int o = 16; o; o >>= 1) m = fmaxf(m, __shfl_xor_sync(0xffffffffu, m, o));

    float ssum = 0.0f;
    for (int k = lane; k <= q; k += 32) ssum += expf(p[k] * scale - m);
    #pragma unroll
    for (int o = 16; o; o >>= 1) ssum += __shfl_xor_sync(0xffffffffu, ssum, o);

    float inv = 1.0f / ssum;
    for (int k = lane; k < SEQ; k += 32)
        p[k] = (k <= q) ? expf(p[k] * scale - m) * inv : 0.0f;
}

// ---------------- launch -------------------------------------------------------
extern "C" void kernel_launch(void* const* d_in, const int* in_sizes, int n_in,
                              void* d_out, int out_size)
{
    const float* X  = (const float*)d_in[0];
    const float* Wq = (const float*)d_in[1];
    const float* Wk = (const float*)d_in[2];
    const float* Wv = (const float*)d_in[3];
    const float* Wo = (const float*)d_in[4];
    float* out = (float*)d_out;

    // 1. QKV projections
    {
        dim3 grid(HID / 128, MROWS / 128, 3);
        qkv_gemm_kernel<<<grid, 256>>>(X, Wq, Wk, Wv);
    }
    // 2. RoPE + transpose
    {
        long long total = (long long)BSZ * NH * SEQ * 64;  // 4,194,304
        rope_transpose_kernel<<<(unsigned)((total + 255) / 256), 256>>>();
    }
    // 3. Scores = Q K^T (lower-triangle blocks only)
    {
        dim3 grid(SEQ / 128, SEQ / 128, NZ);
        score_gemm_kernel<<<grid, 256>>>();
    }
    // 4. Softmax
    {
        unsigned rows = NZ * SEQ;                 // 65536
        softmax_kernel<<<rows / 8, 256>>>();
    }
    // 5. O = P V
    {
        dim3 grid(1, SEQ / 128, NZ);
        pv_gemm_kernel<<<grid, 256>>>();
    }
    // 6. Output projection
    {
        dim3 grid(HID / 128, MROWS / 128);
        out_gemm_kernel<<<grid, 256>>>(Wo, out);
    }
}